// round 16
// baseline (speedup 1.0000x reference)
#include <cuda_runtime.h>
#include <cuda_bf16.h>
#include <math.h>
#include <stdint.h>

#define NB 4
#define NN 5000
#define NKI 4
#define NE 80000
#define ND 512
#define NL 6
#define NLM 3
#define MP 20096            // 157*128 padded rows
#define L2E 1.4426950408889634f
#define NML0 (-57.707801635f)   // -40 * log2(e)
#define PGRID 444               // 148 SM x occ 3

// ---------------- device scratch ----------------
static __device__ __nv_bfloat16 g_xb[MP * ND];
static __device__ __nv_bfloat16 g_y[MP * ND];
static __device__ __nv_bfloat16 g_h[MP * 2 * ND];
static __device__ __nv_bfloat16 g_w1hi[NL * 2 * ND * ND], g_w1lo[NL * 2 * ND * ND];
static __device__ __nv_bfloat16 g_w2hi[NL * 2 * ND * ND], g_w2lo[NL * 2 * ND * ND];
static __device__ __nv_bfloat16 g_wmhi[NLM * ND * ND],    g_wmlo[NLM * ND * ND];
static __device__ int   g_deg[NN], g_rowstart[NN + 1], g_cursor[NN];
static __device__ int   g_esrc[NE];
static __device__ float g_eew[NE];

// ---------------- helpers ----------------
__device__ __forceinline__ uint32_t smem_u32(const void* p) {
    uint32_t a;
    asm("{ .reg .u64 t; cvta.to.shared.u64 t, %1; cvt.u32.u64 %0, t; }" : "=r"(a) : "l"(p));
    return a;
}
__device__ __forceinline__ void cp16(uint32_t sdst, const void* gsrc) {
    asm volatile("cp.async.cg.shared.global [%0], [%1], 16;" :: "r"(sdst), "l"(gsrc));
}
__device__ __forceinline__ void ldsm4(unsigned& r0, unsigned& r1, unsigned& r2, unsigned& r3, uint32_t a) {
    asm volatile("ldmatrix.sync.aligned.m8n8.x4.shared.b16 {%0,%1,%2,%3}, [%4];"
                 : "=r"(r0), "=r"(r1), "=r"(r2), "=r"(r3) : "r"(a));
}
__device__ __forceinline__ void mma_bf16(float* d, const unsigned* a, const unsigned* b) {
    asm volatile("mma.sync.aligned.m16n8k16.row.col.f32.bf16.bf16.f32 "
                 "{%0,%1,%2,%3}, {%4,%5,%6,%7}, {%8,%9}, {%0,%1,%2,%3};"
                 : "+f"(d[0]), "+f"(d[1]), "+f"(d[2]), "+f"(d[3])
                 : "r"(a[0]), "r"(a[1]), "r"(a[2]), "r"(a[3]), "r"(b[0]), "r"(b[1]));
}
__device__ __forceinline__ float ex2f(float x) {
    float r;
    asm("ex2.approx.f32 %0, %1;" : "=f"(r) : "f"(x));
    return r;
}
__device__ __forceinline__ float bflo(uint32_t u) { return __uint_as_float(u << 16); }
__device__ __forceinline__ float bfhi(uint32_t u) { return __uint_as_float(u & 0xFFFF0000u); }

// ---------------- embedding sum -> bf16, fused with edge-degree count ----------------
__global__ void embed_count_kernel(const int* __restrict__ xidx, const float* __restrict__ emb,
                                   const int* __restrict__ dst) {
    int i = blockIdx.x * blockDim.x + threadIdx.x;
    if (i < NE) atomicAdd(&g_deg[dst[i]], 1);
    if (i >= NB * NN * (ND / 4)) return;
    int d4 = i & (ND / 4 - 1);
    int bn = i >> 7;
    int i0 = xidx[bn * NKI + 0], i1 = xidx[bn * NKI + 1];
    int i2 = xidx[bn * NKI + 2], i3 = xidx[bn * NKI + 3];
    const float4* E4 = (const float4*)emb;
    float4 a = E4[i0 * 128 + d4], b = E4[i1 * 128 + d4];
    float4 c = E4[i2 * 128 + d4], d = E4[i3 * 128 + d4];
    float s0 = a.x + b.x + c.x + d.x;
    float s1 = a.y + b.y + c.y + d.y;
    float s2 = a.z + b.z + c.z + d.z;
    float s3 = a.w + b.w + c.w + d.w;
    size_t ob = (size_t)bn * ND + d4 * 4;
    *(__nv_bfloat162*)(g_xb + ob)     = __nv_bfloat162(__float2bfloat16(s0), __float2bfloat16(s1));
    *(__nv_bfloat162*)(g_xb + ob + 2) = __nv_bfloat162(__float2bfloat16(s2), __float2bfloat16(s3));
}

// ---------------- CSR construction ----------------
__global__ void scan_deg_kernel() {
    __shared__ int sh[1024];
    __shared__ int carry;
    if (threadIdx.x == 0) carry = 0;
    __syncthreads();
    for (int base = 0; base < NN; base += 1024) {
        int i = base + threadIdx.x;
        int v = (i < NN) ? g_deg[i] : 0;
        sh[threadIdx.x] = v;
        __syncthreads();
        for (int off = 1; off < 1024; off <<= 1) {
            int t = (threadIdx.x >= off) ? sh[threadIdx.x - off] : 0;
            __syncthreads();
            sh[threadIdx.x] += t;
            __syncthreads();
        }
        if (i < NN) {
            int excl = carry + sh[threadIdx.x] - v;
            g_rowstart[i] = excl;
            g_cursor[i]   = excl;
        }
        int tot = sh[1023];
        __syncthreads();
        if (threadIdx.x == 0) carry += tot;
        __syncthreads();
    }
    if (threadIdx.x == 0) g_rowstart[NN] = carry;
    __syncthreads();
    for (int i = threadIdx.x; i < NN; i += 1024) g_deg[i] = 0;   // reset for next replay
}
__global__ void scatter_edges_kernel(const int* __restrict__ dst, const int* __restrict__ src,
                                     const float* __restrict__ ew) {
    int e = blockIdx.x * blockDim.x + threadIdx.x;
    if (e < NE) {
        int p = atomicAdd(&g_cursor[dst[e]], 1);
        g_esrc[p] = src[e];
        g_eew[p]  = ew[e];
    }
}

// ---------------- SINGLE-PASS segment-softmax (fixed offset 40) ----------------
__global__ void msg_agg_kernel(const __nv_bfloat16* __restrict__ xin,
                               __nv_bfloat16* __restrict__ yout) {
    __shared__ uint32_t soff[128];
    __shared__ float    sew[128];
    int bn = blockIdx.x;
    int b  = bn / NN;
    int n  = bn - b * NN;
    int t  = threadIdx.x;
    const char* xb8 = (const char*)(xin + (size_t)b * NN * ND);
    const uint32_t toff = (uint32_t)(t << 3);

    int s0 = g_rowstart[n], s1 = g_rowstart[n + 1];
    int deg = s1 - s0;

    float den[4] = {0.f, 0.f, 0.f, 0.f}, num[4] = {0.f, 0.f, 0.f, 0.f};

    auto body = [&](uint2 u, float w) {
        float v[4] = {bflo(u.x), bfhi(u.x), bflo(u.y), bfhi(u.y)};
#pragma unroll
        for (int c = 0; c < 4; c++) {
            float r = fmaxf(v[c] + w, 0.f);
            float e = ex2f(fmaf(r, L2E, NML0));
            den[c] += e;
            num[c]  = fmaf(r, e, num[c]);
        }
    };

    if (deg <= 128) {
        if (t < deg) {
            soff[t] = (uint32_t)g_esrc[s0 + t] << 10;
            sew[t]  = g_eew[s0 + t];
        }
        __syncthreads();

        uint2 buf0, buf1, buf2, buf3;
        if (0 < deg) buf0 = *(const uint2*)(xb8 + soff[0] + toff);
        if (1 < deg) buf1 = *(const uint2*)(xb8 + soff[1] + toff);
        if (2 < deg) buf2 = *(const uint2*)(xb8 + soff[2] + toff);
        if (3 < deg) buf3 = *(const uint2*)(xb8 + soff[3] + toff);

        int j = 0;
        for (; j + 4 <= deg; j += 4) {
            uint2 c0 = buf0, c1 = buf1, c2 = buf2, c3 = buf3;
            if (j + 4 < deg) buf0 = *(const uint2*)(xb8 + soff[j + 4] + toff);
            if (j + 5 < deg) buf1 = *(const uint2*)(xb8 + soff[j + 5] + toff);
            if (j + 6 < deg) buf2 = *(const uint2*)(xb8 + soff[j + 6] + toff);
            if (j + 7 < deg) buf3 = *(const uint2*)(xb8 + soff[j + 7] + toff);
            body(c0, sew[j + 0]); body(c1, sew[j + 1]); body(c2, sew[j + 2]); body(c3, sew[j + 3]);
        }
        for (; j < deg; j++)
            body(*(const uint2*)(xb8 + soff[j] + toff), sew[j]);
    } else {
        for (int chunk = s0; chunk < s1; chunk += 128) {
            int cnt = min(128, s1 - chunk);
            __syncthreads();
            if (t < cnt) {
                soff[t] = (uint32_t)g_esrc[chunk + t] << 10;
                sew[t]  = g_eew[chunk + t];
            }
            __syncthreads();
            for (int j = 0; j < cnt; j++)
                body(*(const uint2*)(xb8 + soff[j] + toff), sew[j]);
        }
    }

    uint2 us = *(const uint2*)(xb8 + ((uint32_t)n << 10) + toff);
    float xi[4] = {bflo(us.x), bfhi(us.x), bflo(us.y), bfhi(us.y)};
    float o[4];
#pragma unroll
    for (int c = 0; c < 4; c++) {
        float agg = fmaf(1e-7f, den[c], num[c]) / (den[c] + 1e-30f);
        o[c] = agg + xi[c];
    }

    size_t ob = (size_t)bn * ND + t * 4;
    *(__nv_bfloat162*)(yout + ob)     = __nv_bfloat162(__float2bfloat16(o[0]), __float2bfloat16(o[1]));
    *(__nv_bfloat162*)(yout + ob + 2) = __nv_bfloat162(__float2bfloat16(o[2]), __float2bfloat16(o[3]));
}

// ---------------- fused weight transpose + bf16 split (all 15 matrices) ----------------
__global__ void transpose_split_all_kernel(const float* __restrict__ W1,
                                           const float* __restrict__ W2,
                                           const float* __restrict__ Wm) {
    __shared__ float t[32][33];
    int z = blockIdx.z;
    const float* W; __nv_bfloat16 *Thi, *Tlo; int Kd, Nd;
    if (z < NL) {
        Kd = ND; Nd = 2 * ND;
        W   = W1 + (size_t)z * ND * 2 * ND;
        Thi = g_w1hi + (size_t)z * 2 * ND * ND;
        Tlo = g_w1lo + (size_t)z * 2 * ND * ND;
    } else if (z < 2 * NL) {
        int l = z - NL;
        Kd = 2 * ND; Nd = ND;
        W   = W2 + (size_t)l * 2 * ND * ND;
        Thi = g_w2hi + (size_t)l * ND * 2 * ND;
        Tlo = g_w2lo + (size_t)l * ND * 2 * ND;
    } else {
        int l = z - 2 * NL;
        Kd = ND; Nd = ND;
        W   = Wm + (size_t)l * ND * ND;
        Thi = g_wmhi + (size_t)l * ND * ND;
        Tlo = g_wmlo + (size_t)l * ND * ND;
    }
    int n0 = blockIdx.x * 32, k0 = blockIdx.y * 32;
    if (n0 >= Nd || k0 >= Kd) return;
    int tx = threadIdx.x, ty = threadIdx.y;
#pragma unroll
    for (int r = 0; r < 32; r += 8)
        t[ty + r][tx] = W[(size_t)(k0 + ty + r) * Nd + n0 + tx];
    __syncthreads();
#pragma unroll
    for (int r = 0; r < 32; r += 8) {
        float v = t[tx][ty + r];
        __nv_bfloat16 h = __float2bfloat16(v);
        size_t o = (size_t)(n0 + ty + r) * Kd + k0 + tx;
        Thi[o] = h;
        Tlo[o] = __float2bfloat16(v - __bfloat162float(h));
    }
}

// ---------------- persistent 2-term split GEMM, 128x64 tiles, occ-3 ----------------
#define TPITCH 80
#define OFF_BH 10240
#define OFF_BL 15360
#define STG 20480
#define GSMEM (3 * STG)

template <int MODE>
__device__ __forceinline__ float ep_apply(float v, float gv, float bv) {
    if (MODE == 0) return fmaxf(v * 0.9999950000374997f * gv + bv, 0.f);
    if (MODE == 1) return fmaxf(v, 0.f);
    return 0.5f * v * (1.f + erff(v * 0.7071067811865475f));
}

template <int MODE>
__global__ void __launch_bounds__(256, 3) bfgemm2_kernel(
    int N, int K, int ntiles, int nxtiles,
    const __nv_bfloat16* __restrict__ A,
    const __nv_bfloat16* __restrict__ Bhi, const __nv_bfloat16* __restrict__ Blo,
    __nv_bfloat16* __restrict__ Cb,
    const float* __restrict__ bias, const float* __restrict__ gsc, const float* __restrict__ bsh,
    const float* __restrict__ wout, const float* __restrict__ boutp, float* __restrict__ outp)
{
    extern __shared__ char smem[];
    const uint32_t sb = smem_u32(smem);
    const int tid = threadIdx.x, lane = tid & 31, warp = tid >> 5;
    const int wm = warp >> 1, wn = warp & 1;       // 4 x 2 warps, each 32x32
    const int KT = K >> 5;

    const uint32_t arow = (uint32_t)(wm * 32 + (lane & 15));
    const uint32_t brow = (uint32_t)(wn * 32 + (lane & 7) + ((lane >> 4) << 3));
    const uint32_t akhi = (uint32_t)((lane >> 4) << 3);
    const uint32_t bkhi = (uint32_t)(((lane >> 3) & 1) << 3);

    for (int tile = blockIdx.x; tile < ntiles; tile += gridDim.x) {
        const int bn0 = (tile % nxtiles) * 64;
        const int bm0 = (tile / nxtiles) * 128;

        float acc[2][4][4];
#pragma unroll
        for (int i = 0; i < 2; i++)
#pragma unroll
            for (int j = 0; j < 4; j++)
#pragma unroll
                for (int c = 0; c < 4; c++) acc[i][j][c] = 0.f;

        auto load_stage = [&](int st, int kt) {
            uint32_t base = sb + st * STG;
            int k0 = kt * 32;
#pragma unroll
            for (int p = 0; p < 2; p++) {
                int cid = tid + 256 * p;
                int r = cid >> 2, c = cid & 3;
                cp16(base + (uint32_t)(r * TPITCH + c * 16),
                     A + (size_t)(bm0 + r) * K + k0 + c * 8);
            }
            {
                int r = tid >> 2, c = tid & 3;
                uint32_t so = (uint32_t)(r * TPITCH + c * 16);
                size_t gb = (size_t)(bn0 + r) * K + k0 + c * 8;
                cp16(base + OFF_BH + so, Bhi + gb);
                cp16(base + OFF_BL + so, Blo + gb);
            }
            asm volatile("cp.async.commit_group;");
        };

        load_stage(0, 0);
        load_stage(1, 1);

        for (int kt = 0; kt < KT; kt++) {
            asm volatile("cp.async.wait_group 1;");
            __syncthreads();
            uint32_t base = sb + (kt % 3) * STG;

#pragma unroll
            for (int ks = 0; ks < 2; ks++) {
                unsigned a[2][4], bh[4][2], bl[4][2];
                uint32_t acb = (uint32_t)((ks * 16 + akhi) * 2);
                uint32_t bcb = (uint32_t)((ks * 16 + bkhi) * 2);
#pragma unroll
                for (int mt = 0; mt < 2; mt++)
                    ldsm4(a[mt][0], a[mt][1], a[mt][2], a[mt][3],
                          base + (arow + mt * 16) * TPITCH + acb);
                ldsm4(bh[0][0], bh[0][1], bh[1][0], bh[1][1], base + OFF_BH + brow * TPITCH + bcb);
                ldsm4(bh[2][0], bh[2][1], bh[3][0], bh[3][1], base + OFF_BH + (brow + 16) * TPITCH + bcb);
                ldsm4(bl[0][0], bl[0][1], bl[1][0], bl[1][1], base + OFF_BL + brow * TPITCH + bcb);
                ldsm4(bl[2][0], bl[2][1], bl[3][0], bl[3][1], base + OFF_BL + (brow + 16) * TPITCH + bcb);
#pragma unroll
                for (int mt = 0; mt < 2; mt++)
#pragma unroll
                    for (int nt = 0; nt < 4; nt++) {
                        mma_bf16(acc[mt][nt], a[mt], bh[nt]);
                        mma_bf16(acc[mt][nt], a[mt], bl[nt]);
                    }
            }

            if (kt + 2 < KT) load_stage((kt + 2) % 3, kt + 2);
        }

        if (MODE != 3) {
#pragma unroll
            for (int nt = 0; nt < 4; nt++) {
                int c = bn0 + wn * 32 + nt * 8 + (lane & 3) * 2;
                float bi0 = bias[c], bi1 = bias[c + 1];
                float g0 = 0.f, g1 = 0.f, s0 = 0.f, s1 = 0.f;
                if (MODE == 0) { g0 = gsc[c]; g1 = gsc[c + 1]; s0 = bsh[c]; s1 = bsh[c + 1]; }
#pragma unroll
                for (int mt = 0; mt < 2; mt++) {
                    size_t r0 = (size_t)(bm0 + wm * 32 + mt * 16 + (lane >> 2));
                    size_t r1 = r0 + 8;
                    float v00 = ep_apply<MODE>(acc[mt][nt][0] + bi0, g0, s0);
                    float v01 = ep_apply<MODE>(acc[mt][nt][1] + bi1, g1, s1);
                    float v10 = ep_apply<MODE>(acc[mt][nt][2] + bi0, g0, s0);
                    float v11 = ep_apply<MODE>(acc[mt][nt][3] + bi1, g1, s1);
                    *(__nv_bfloat162*)(Cb + r0 * N + c) =
                        __nv_bfloat162(__float2bfloat16(v00), __float2bfloat16(v01));
                    *(__nv_bfloat162*)(Cb + r1 * N + c) =
                        __nv_bfloat162(__float2bfloat16(v10), __float2bfloat16(v11));
                }
            }
            __syncthreads();   // protect smem stages before next tile's preload
        } else {
            __syncthreads();
            float* rowacc   = (float*)smem;
            float* batchacc = (float*)(smem + 512);
            if (tid < 128) rowacc[tid] = 0.f;
            if (tid >= 128 && tid < 132) batchacc[tid - 128] = 0.f;
            __syncthreads();
#pragma unroll
            for (int mt = 0; mt < 2; mt++) {
                float hs0 = 0.f, hs1 = 0.f;
#pragma unroll
                for (int nt = 0; nt < 4; nt++) {
                    int c = bn0 + wn * 32 + nt * 8 + (lane & 3) * 2;
                    float bi0 = bias[c], bi1 = bias[c + 1];
                    float v00 = ep_apply<2>(acc[mt][nt][0] + bi0, 0.f, 0.f);
                    float v01 = ep_apply<2>(acc[mt][nt][1] + bi1, 0.f, 0.f);
                    float v10 = ep_apply<2>(acc[mt][nt][2] + bi0, 0.f, 0.f);
                    float v11 = ep_apply<2>(acc[mt][nt][3] + bi1, 0.f, 0.f);
                    float w0 = wout[c], w1 = wout[c + 1];
                    hs0 += v00 * w0 + v01 * w1;
                    hs1 += v10 * w0 + v11 * w1;
                }
                int lr = wm * 32 + mt * 16 + (lane >> 2);
                atomicAdd(&rowacc[lr], hs0);
                atomicAdd(&rowacc[lr + 8], hs1);
            }
            __syncthreads();
            if (tid < 128) {
                int gr = bm0 + tid;
                if (gr < NB * NN) {
                    float contrib = rowacc[tid];
                    if (tile == 0) contrib += boutp[0];
                    atomicAdd(&batchacc[gr / NN], contrib);
                }
            }
            __syncthreads();
            if (tid < 4) atomicAdd(&outp[tid], batchacc[tid] * (1.f / NN));
            __syncthreads();   // protect smem before next tile's preload
        }
    }
}

// ---------------- LayerNorm (bf16 in/out) ----------------
__global__ void ln_kernel(const __nv_bfloat16* __restrict__ xin, __nv_bfloat16* __restrict__ yout,
                          const float* __restrict__ g, const float* __restrict__ bta) {
    int row = blockIdx.x;
    int t = threadIdx.x;
    __shared__ float red[4];
    uint2 u = *(const uint2*)(xin + (size_t)row * ND + t * 4);
    float v0 = bflo(u.x), v1 = bfhi(u.x), v2 = bflo(u.y), v3 = bfhi(u.y);

    float s = v0 + v1 + v2 + v3;
#pragma unroll
    for (int off = 16; off > 0; off >>= 1) s += __shfl_xor_sync(0xffffffff, s, off);
    if ((t & 31) == 0) red[t >> 5] = s;
    __syncthreads();
    float mu = (red[0] + red[1] + red[2] + red[3]) * (1.f / ND);
    __syncthreads();

    float d0 = v0 - mu, d1 = v1 - mu, d2 = v2 - mu, d3 = v3 - mu;
    float q = d0 * d0 + d1 * d1 + d2 * d2 + d3 * d3;
#pragma unroll
    for (int off = 16; off > 0; off >>= 1) q += __shfl_xor_sync(0xffffffff, q, off);
    if ((t & 31) == 0) red[t >> 5] = q;
    __syncthreads();
    float var = (red[0] + red[1] + red[2] + red[3]) * (1.f / ND);
    float rs  = rsqrtf(var + 1e-5f);

    float4 gg = ((const float4*)g)[t];
    float4 bb = ((const float4*)bta)[t];
    float o0 = d0 * rs * gg.x + bb.x;
    float o1 = d1 * rs * gg.y + bb.y;
    float o2 = d2 * rs * gg.z + bb.z;
    float o3 = d3 * rs * gg.w + bb.w;

    size_t ob = (size_t)row * ND + t * 4;
    *(__nv_bfloat162*)(yout + ob)     = __nv_bfloat162(__float2bfloat16(o0), __float2bfloat16(o1));
    *(__nv_bfloat162*)(yout + ob + 2) = __nv_bfloat162(__float2bfloat16(o2), __float2bfloat16(o3));
}

__global__ void zero_out_kernel(float* out) {
    if (threadIdx.x < NB) out[threadIdx.x] = 0.f;
}

// ---------------- launch ----------------
extern "C" void kernel_launch(void* const* d_in, const int* in_sizes, int n_in,
                              void* d_out, int out_size) {
    const int*   x_idx = (const int*)d_in[0];
    const int*   eidx  = (const int*)d_in[1];
    const float* ew    = (const float*)d_in[2];
    const float* emb   = (const float*)d_in[3];
    const float* W1    = (const float*)d_in[4];
    const float* b1    = (const float*)d_in[5];
    const float* g1    = (const float*)d_in[6];
    const float* be1   = (const float*)d_in[7];
    const float* W2    = (const float*)d_in[8];
    const float* b2    = (const float*)d_in[9];
    const float* ln_g  = (const float*)d_in[10];
    const float* ln_b  = (const float*)d_in[11];
    const float* Wm    = (const float*)d_in[12];
    const float* bm    = (const float*)d_in[13];
    const float* Wout  = (const float*)d_in[14];
    const float* bout  = (const float*)d_in[15];
    float* out = (float*)d_out;

    const int* src = eidx;
    const int* dst = eidx + NE;

    __nv_bfloat16 *pxb, *py, *ph, *w1hi, *w1lo, *w2hi, *w2lo, *wmhi, *wmlo;
    cudaGetSymbolAddress((void**)&pxb,  g_xb);
    cudaGetSymbolAddress((void**)&py,   g_y);
    cudaGetSymbolAddress((void**)&ph,   g_h);
    cudaGetSymbolAddress((void**)&w1hi, g_w1hi);
    cudaGetSymbolAddress((void**)&w1lo, g_w1lo);
    cudaGetSymbolAddress((void**)&w2hi, g_w2hi);
    cudaGetSymbolAddress((void**)&w2lo, g_w2lo);
    cudaGetSymbolAddress((void**)&wmhi, g_wmhi);
    cudaGetSymbolAddress((void**)&wmlo, g_wmlo);

    cudaFuncSetAttribute(bfgemm2_kernel<0>, cudaFuncAttributeMaxDynamicSharedMemorySize, GSMEM);
    cudaFuncSetAttribute(bfgemm2_kernel<1>, cudaFuncAttributeMaxDynamicSharedMemorySize, GSMEM);
    cudaFuncSetAttribute(bfgemm2_kernel<2>, cudaFuncAttributeMaxDynamicSharedMemorySize, GSMEM);
    cudaFuncSetAttribute(bfgemm2_kernel<3>, cudaFuncAttributeMaxDynamicSharedMemorySize, GSMEM);

    embed_count_kernel<<<(NB * NN * (ND / 4) + 255) / 256, 256>>>(x_idx, emb, dst);
    scan_deg_kernel<<<1, 1024>>>();
    scatter_edges_kernel<<<(NE + 255) / 256, 256>>>(dst, src, ew);
    msg_agg_kernel<<<NB * NN, 128>>>(pxb, py);   // layer 0
    transpose_split_all_kernel<<<dim3(32, 32, 2 * NL + NLM), dim3(32, 8)>>>(W1, W2, Wm);

    const int nt1 = 16 * (MP / 128);   // GEMM1 tiles: 2512
    const int nt2 = 8 * (MP / 128);    // GEMM2/MLP tiles: 1256

    for (int l = 0; l < NL; l++) {
        if (l > 0) msg_agg_kernel<<<NB * NN, 128>>>(pxb, py);
        bfgemm2_kernel<0><<<PGRID, 256, GSMEM>>>(
            2 * ND, ND, nt1, 16, py,
            w1hi + (size_t)l * 2 * ND * ND, w1lo + (size_t)l * 2 * ND * ND,
            ph,
            b1 + (size_t)l * 2 * ND, g1 + (size_t)l * 2 * ND, be1 + (size_t)l * 2 * ND,
            nullptr, nullptr, nullptr);
        bfgemm2_kernel<1><<<PGRID, 256, GSMEM>>>(
            ND, 2 * ND, nt2, 8, ph,
            w2hi + (size_t)l * ND * 2 * ND, w2lo + (size_t)l * ND * 2 * ND,
            pxb,
            b2 + (size_t)l * ND, nullptr, nullptr,
            nullptr, nullptr, nullptr);
    }

    ln_kernel<<<NB * NN, 128>>>(pxb, py, ln_g, ln_b);

    bfgemm2_kernel<2><<<PGRID, 256, GSMEM>>>(
        ND, ND, nt2, 8, py, wmhi, wmlo, ph, bm, nullptr, nullptr, nullptr, nullptr, nullptr);
    bfgemm2_kernel<2><<<PGRID, 256, GSMEM>>>(
        ND, ND, nt2, 8, ph, wmhi + (size_t)ND * ND, wmlo + (size_t)ND * ND,
        py, bm + ND, nullptr, nullptr, nullptr, nullptr, nullptr);

    zero_out_kernel<<<1, 32>>>(out);
    bfgemm2_kernel<3><<<PGRID, 256, GSMEM>>>(
        ND, ND, nt2, 8, py, wmhi + (size_t)2 * ND * ND, wmlo + (size_t)2 * ND * ND,
        nullptr, bm + 2 * ND, nullptr, nullptr, Wout, bout, out);
}

// round 17
// speedup vs baseline: 1.0731x; 1.0731x over previous
#include <cuda_runtime.h>
#include <cuda_bf16.h>
#include <math.h>
#include <stdint.h>

#define NB 4
#define NN 5000
#define NKI 4
#define NE 80000
#define ND 512
#define NL 6
#define NLM 3
#define MP 20096            // 157*128 padded rows
#define L2E 1.4426950408889634f
#define NML0 (-57.707801635f)   // -40 * log2(e)

// ---------------- device scratch ----------------
static __device__ __nv_bfloat16 g_xb[MP * ND];
static __device__ __nv_bfloat16 g_y[MP * ND];
static __device__ __nv_bfloat16 g_h[MP * 2 * ND];
static __device__ __nv_bfloat16 g_w1hi[NL * 2 * ND * ND], g_w1lo[NL * 2 * ND * ND];
static __device__ __nv_bfloat16 g_w2hi[NL * 2 * ND * ND], g_w2lo[NL * 2 * ND * ND];
static __device__ __nv_bfloat16 g_wmhi[NLM * ND * ND],    g_wmlo[NLM * ND * ND];
static __device__ int   g_deg[NN], g_rowstart[NN + 1], g_cursor[NN];
static __device__ int   g_esrc[NE];
static __device__ float g_eew[NE];

// ---------------- helpers ----------------
__device__ __forceinline__ uint32_t smem_u32(const void* p) {
    uint32_t a;
    asm("{ .reg .u64 t; cvta.to.shared.u64 t, %1; cvt.u32.u64 %0, t; }" : "=r"(a) : "l"(p));
    return a;
}
__device__ __forceinline__ void cp16(uint32_t sdst, const void* gsrc) {
    asm volatile("cp.async.cg.shared.global [%0], [%1], 16;" :: "r"(sdst), "l"(gsrc));
}
__device__ __forceinline__ void ldsm4(unsigned& r0, unsigned& r1, unsigned& r2, unsigned& r3, uint32_t a) {
    asm volatile("ldmatrix.sync.aligned.m8n8.x4.shared.b16 {%0,%1,%2,%3}, [%4];"
                 : "=r"(r0), "=r"(r1), "=r"(r2), "=r"(r3) : "r"(a));
}
__device__ __forceinline__ void mma_bf16(float* d, const unsigned* a, const unsigned* b) {
    asm volatile("mma.sync.aligned.m16n8k16.row.col.f32.bf16.bf16.f32 "
                 "{%0,%1,%2,%3}, {%4,%5,%6,%7}, {%8,%9}, {%0,%1,%2,%3};"
                 : "+f"(d[0]), "+f"(d[1]), "+f"(d[2]), "+f"(d[3])
                 : "r"(a[0]), "r"(a[1]), "r"(a[2]), "r"(a[3]), "r"(b[0]), "r"(b[1]));
}
__device__ __forceinline__ float ex2f(float x) {
    float r;
    asm("ex2.approx.f32 %0, %1;" : "=f"(r) : "f"(x));
    return r;
}
__device__ __forceinline__ float bflo(uint32_t u) { return __uint_as_float(u << 16); }
__device__ __forceinline__ float bfhi(uint32_t u) { return __uint_as_float(u & 0xFFFF0000u); }

// ---------------- embedding sum -> bf16, fused with edge-degree count ----------------
__global__ void embed_count_kernel(const int* __restrict__ xidx, const float* __restrict__ emb,
                                   const int* __restrict__ dst) {
    int i = blockIdx.x * blockDim.x + threadIdx.x;
    if (i < NE) atomicAdd(&g_deg[dst[i]], 1);
    if (i >= NB * NN * (ND / 4)) return;
    int d4 = i & (ND / 4 - 1);
    int bn = i >> 7;
    int i0 = xidx[bn * NKI + 0], i1 = xidx[bn * NKI + 1];
    int i2 = xidx[bn * NKI + 2], i3 = xidx[bn * NKI + 3];
    const float4* E4 = (const float4*)emb;
    float4 a = E4[i0 * 128 + d4], b = E4[i1 * 128 + d4];
    float4 c = E4[i2 * 128 + d4], d = E4[i3 * 128 + d4];
    float s0 = a.x + b.x + c.x + d.x;
    float s1 = a.y + b.y + c.y + d.y;
    float s2 = a.z + b.z + c.z + d.z;
    float s3 = a.w + b.w + c.w + d.w;
    size_t ob = (size_t)bn * ND + d4 * 4;
    *(__nv_bfloat162*)(g_xb + ob)     = __nv_bfloat162(__float2bfloat16(s0), __float2bfloat16(s1));
    *(__nv_bfloat162*)(g_xb + ob + 2) = __nv_bfloat162(__float2bfloat16(s2), __float2bfloat16(s3));
}

// ---------------- CSR construction ----------------
__global__ void scan_deg_kernel() {
    __shared__ int sh[1024];
    __shared__ int carry;
    if (threadIdx.x == 0) carry = 0;
    __syncthreads();
    for (int base = 0; base < NN; base += 1024) {
        int i = base + threadIdx.x;
        int v = (i < NN) ? g_deg[i] : 0;
        sh[threadIdx.x] = v;
        __syncthreads();
        for (int off = 1; off < 1024; off <<= 1) {
            int t = (threadIdx.x >= off) ? sh[threadIdx.x - off] : 0;
            __syncthreads();
            sh[threadIdx.x] += t;
            __syncthreads();
        }
        if (i < NN) {
            int excl = carry + sh[threadIdx.x] - v;
            g_rowstart[i] = excl;
            g_cursor[i]   = excl;
        }
        int tot = sh[1023];
        __syncthreads();
        if (threadIdx.x == 0) carry += tot;
        __syncthreads();
    }
    if (threadIdx.x == 0) g_rowstart[NN] = carry;
    __syncthreads();
    for (int i = threadIdx.x; i < NN; i += 1024) g_deg[i] = 0;   // reset for next replay
}
__global__ void scatter_edges_kernel(const int* __restrict__ dst, const int* __restrict__ src,
                                     const float* __restrict__ ew) {
    int e = blockIdx.x * blockDim.x + threadIdx.x;
    if (e < NE) {
        int p = atomicAdd(&g_cursor[dst[e]], 1);
        g_esrc[p] = src[e];
        g_eew[p]  = ew[e];
    }
}

// ---------------- SINGLE-PASS segment-softmax (fixed offset 40) ----------------
__global__ void msg_agg_kernel(const __nv_bfloat16* __restrict__ xin,
                               __nv_bfloat16* __restrict__ yout) {
    __shared__ uint32_t soff[128];
    __shared__ float    sew[128];
    int bn = blockIdx.x;
    int b  = bn / NN;
    int n  = bn - b * NN;
    int t  = threadIdx.x;
    const char* xb8 = (const char*)(xin + (size_t)b * NN * ND);
    const uint32_t toff = (uint32_t)(t << 3);

    int s0 = g_rowstart[n], s1 = g_rowstart[n + 1];
    int deg = s1 - s0;

    float den[4] = {0.f, 0.f, 0.f, 0.f}, num[4] = {0.f, 0.f, 0.f, 0.f};

    auto body = [&](uint2 u, float w) {
        float v[4] = {bflo(u.x), bfhi(u.x), bflo(u.y), bfhi(u.y)};
#pragma unroll
        for (int c = 0; c < 4; c++) {
            float r = fmaxf(v[c] + w, 0.f);
            float e = ex2f(fmaf(r, L2E, NML0));
            den[c] += e;
            num[c]  = fmaf(r, e, num[c]);
        }
    };

    if (deg <= 128) {
        if (t < deg) {
            soff[t] = (uint32_t)g_esrc[s0 + t] << 10;
            sew[t]  = g_eew[s0 + t];
        }
        __syncthreads();
        // plain unrolled loop: addresses come from smem (no dependent chain);
        // ptxas batches the independent LDGs within each unrolled group.
#pragma unroll 4
        for (int j = 0; j < deg; j++)
            body(*(const uint2*)(xb8 + soff[j] + toff), sew[j]);
    } else {
        for (int chunk = s0; chunk < s1; chunk += 128) {
            int cnt = min(128, s1 - chunk);
            __syncthreads();
            if (t < cnt) {
                soff[t] = (uint32_t)g_esrc[chunk + t] << 10;
                sew[t]  = g_eew[chunk + t];
            }
            __syncthreads();
#pragma unroll 4
            for (int j = 0; j < cnt; j++)
                body(*(const uint2*)(xb8 + soff[j] + toff), sew[j]);
        }
    }

    uint2 us = *(const uint2*)(xb8 + ((uint32_t)n << 10) + toff);
    float xi[4] = {bflo(us.x), bfhi(us.x), bflo(us.y), bfhi(us.y)};
    float o[4];
#pragma unroll
    for (int c = 0; c < 4; c++) {
        float agg = __fdividef(fmaf(1e-7f, den[c], num[c]), den[c] + 1e-30f);
        o[c] = agg + xi[c];
    }

    size_t ob = (size_t)bn * ND + t * 4;
    *(__nv_bfloat162*)(yout + ob)     = __nv_bfloat162(__float2bfloat16(o[0]), __float2bfloat16(o[1]));
    *(__nv_bfloat162*)(yout + ob + 2) = __nv_bfloat162(__float2bfloat16(o[2]), __float2bfloat16(o[3]));
}

// ---------------- fused weight transpose + bf16 split (all 15 matrices) ----------------
__global__ void transpose_split_all_kernel(const float* __restrict__ W1,
                                           const float* __restrict__ W2,
                                           const float* __restrict__ Wm) {
    __shared__ float t[32][33];
    int z = blockIdx.z;
    const float* W; __nv_bfloat16 *Thi, *Tlo; int Kd, Nd;
    if (z < NL) {
        Kd = ND; Nd = 2 * ND;
        W   = W1 + (size_t)z * ND * 2 * ND;
        Thi = g_w1hi + (size_t)z * 2 * ND * ND;
        Tlo = g_w1lo + (size_t)z * 2 * ND * ND;
    } else if (z < 2 * NL) {
        int l = z - NL;
        Kd = 2 * ND; Nd = ND;
        W   = W2 + (size_t)l * 2 * ND * ND;
        Thi = g_w2hi + (size_t)l * ND * 2 * ND;
        Tlo = g_w2lo + (size_t)l * ND * 2 * ND;
    } else {
        int l = z - 2 * NL;
        Kd = ND; Nd = ND;
        W   = Wm + (size_t)l * ND * ND;
        Thi = g_wmhi + (size_t)l * ND * ND;
        Tlo = g_wmlo + (size_t)l * ND * ND;
    }
    int n0 = blockIdx.x * 32, k0 = blockIdx.y * 32;
    if (n0 >= Nd || k0 >= Kd) return;
    int tx = threadIdx.x, ty = threadIdx.y;
#pragma unroll
    for (int r = 0; r < 32; r += 8)
        t[ty + r][tx] = W[(size_t)(k0 + ty + r) * Nd + n0 + tx];
    __syncthreads();
#pragma unroll
    for (int r = 0; r < 32; r += 8) {
        float v = t[tx][ty + r];
        __nv_bfloat16 h = __float2bfloat16(v);
        size_t o = (size_t)(n0 + ty + r) * Kd + k0 + tx;
        Thi[o] = h;
        Tlo[o] = __float2bfloat16(v - __bfloat162float(h));
    }
}

// ---------------- 2-term split GEMM, 128x64 tiles, occ-3 (R15 proven config) ----------------
#define TPITCH 80
#define OFF_BH 10240
#define OFF_BL 15360
#define STG 20480
#define GSMEM (3 * STG)

template <int MODE>
__device__ __forceinline__ float ep_apply(float v, float gv, float bv) {
    if (MODE == 0) return fmaxf(v * 0.9999950000374997f * gv + bv, 0.f);
    if (MODE == 1) return fmaxf(v, 0.f);
    return 0.5f * v * (1.f + erff(v * 0.7071067811865475f));
}

template <int MODE>
__global__ void __launch_bounds__(256, 3) bfgemm2_kernel(
    int N, int K,
    const __nv_bfloat16* __restrict__ A,
    const __nv_bfloat16* __restrict__ Bhi, const __nv_bfloat16* __restrict__ Blo,
    __nv_bfloat16* __restrict__ Cb,
    const float* __restrict__ bias, const float* __restrict__ gsc, const float* __restrict__ bsh,
    const float* __restrict__ wout, const float* __restrict__ boutp, float* __restrict__ outp)
{
    extern __shared__ char smem[];
    const uint32_t sb = smem_u32(smem);
    const int tid = threadIdx.x, lane = tid & 31, warp = tid >> 5;
    const int wm = warp >> 1, wn = warp & 1;       // 4 x 2 warps, each 32x32
    const int bm0 = blockIdx.y * 128, bn0 = blockIdx.x * 64;
    const int KT = K >> 5;

    float acc[2][4][4];
#pragma unroll
    for (int i = 0; i < 2; i++)
#pragma unroll
        for (int j = 0; j < 4; j++)
#pragma unroll
            for (int c = 0; c < 4; c++) acc[i][j][c] = 0.f;

    auto load_stage = [&](int st, int kt) {
        uint32_t base = sb + st * STG;
        int k0 = kt * 32;
#pragma unroll
        for (int p = 0; p < 2; p++) {
            int cid = tid + 256 * p;
            int r = cid >> 2, c = cid & 3;
            cp16(base + (uint32_t)(r * TPITCH + c * 16),
                 A + (size_t)(bm0 + r) * K + k0 + c * 8);
        }
        {
            int r = tid >> 2, c = tid & 3;
            uint32_t so = (uint32_t)(r * TPITCH + c * 16);
            size_t gb = (size_t)(bn0 + r) * K + k0 + c * 8;
            cp16(base + OFF_BH + so, Bhi + gb);
            cp16(base + OFF_BL + so, Blo + gb);
        }
        asm volatile("cp.async.commit_group;");
    };

    load_stage(0, 0);
    load_stage(1, 1);

    const uint32_t arow = (uint32_t)(wm * 32 + (lane & 15));
    const uint32_t brow = (uint32_t)(wn * 32 + (lane & 7) + ((lane >> 4) << 3));
    const uint32_t akhi = (uint32_t)((lane >> 4) << 3);
    const uint32_t bkhi = (uint32_t)(((lane >> 3) & 1) << 3);

    for (int kt = 0; kt < KT; kt++) {
        asm volatile("cp.async.wait_group 1;");
        __syncthreads();
        uint32_t base = sb + (kt % 3) * STG;

#pragma unroll
        for (int ks = 0; ks < 2; ks++) {
            unsigned a[2][4], bh[4][2], bl[4][2];
            uint32_t acb = (uint32_t)((ks * 16 + akhi) * 2);
            uint32_t bcb = (uint32_t)((ks * 16 + bkhi) * 2);
#pragma unroll
            for (int mt = 0; mt < 2; mt++)
                ldsm4(a[mt][0], a[mt][1], a[mt][2], a[mt][3],
                      base + (arow + mt * 16) * TPITCH + acb);
            ldsm4(bh[0][0], bh[0][1], bh[1][0], bh[1][1], base + OFF_BH + brow * TPITCH + bcb);
            ldsm4(bh[2][0], bh[2][1], bh[3][0], bh[3][1], base + OFF_BH + (brow + 16) * TPITCH + bcb);
            ldsm4(bl[0][0], bl[0][1], bl[1][0], bl[1][1], base + OFF_BL + brow * TPITCH + bcb);
            ldsm4(bl[2][0], bl[2][1], bl[3][0], bl[3][1], base + OFF_BL + (brow + 16) * TPITCH + bcb);
#pragma unroll
            for (int mt = 0; mt < 2; mt++)
#pragma unroll
                for (int nt = 0; nt < 4; nt++) {
                    mma_bf16(acc[mt][nt], a[mt], bh[nt]);
                    mma_bf16(acc[mt][nt], a[mt], bl[nt]);
                }
        }

        if (kt + 2 < KT) load_stage((kt + 2) % 3, kt + 2);
    }

    if (MODE != 3) {
#pragma unroll
        for (int nt = 0; nt < 4; nt++) {
            int c = bn0 + wn * 32 + nt * 8 + (lane & 3) * 2;
            float bi0 = bias[c], bi1 = bias[c + 1];
            float g0 = 0.f, g1 = 0.f, s0 = 0.f, s1 = 0.f;
            if (MODE == 0) { g0 = gsc[c]; g1 = gsc[c + 1]; s0 = bsh[c]; s1 = bsh[c + 1]; }
#pragma unroll
            for (int mt = 0; mt < 2; mt++) {
                size_t r0 = (size_t)(bm0 + wm * 32 + mt * 16 + (lane >> 2));
                size_t r1 = r0 + 8;
                float v00 = ep_apply<MODE>(acc[mt][nt][0] + bi0, g0, s0);
                float v01 = ep_apply<MODE>(acc[mt][nt][1] + bi1, g1, s1);
                float v10 = ep_apply<MODE>(acc[mt][nt][2] + bi0, g0, s0);
                float v11 = ep_apply<MODE>(acc[mt][nt][3] + bi1, g1, s1);
                *(__nv_bfloat162*)(Cb + r0 * N + c) =
                    __nv_bfloat162(__float2bfloat16(v00), __float2bfloat16(v01));
                *(__nv_bfloat162*)(Cb + r1 * N + c) =
                    __nv_bfloat162(__float2bfloat16(v10), __float2bfloat16(v11));
            }
        }
    } else {
        __syncthreads();
        float* rowacc   = (float*)smem;
        float* batchacc = (float*)(smem + 512);
        if (tid < 128) rowacc[tid] = 0.f;
        if (tid >= 128 && tid < 132) batchacc[tid - 128] = 0.f;
        __syncthreads();
#pragma unroll
        for (int mt = 0; mt < 2; mt++) {
            float hs0 = 0.f, hs1 = 0.f;
#pragma unroll
            for (int nt = 0; nt < 4; nt++) {
                int c = bn0 + wn * 32 + nt * 8 + (lane & 3) * 2;
                float bi0 = bias[c], bi1 = bias[c + 1];
                float v00 = ep_apply<2>(acc[mt][nt][0] + bi0, 0.f, 0.f);
                float v01 = ep_apply<2>(acc[mt][nt][1] + bi1, 0.f, 0.f);
                float v10 = ep_apply<2>(acc[mt][nt][2] + bi0, 0.f, 0.f);
                float v11 = ep_apply<2>(acc[mt][nt][3] + bi1, 0.f, 0.f);
                float w0 = wout[c], w1 = wout[c + 1];
                hs0 += v00 * w0 + v01 * w1;
                hs1 += v10 * w0 + v11 * w1;
            }
            int lr = wm * 32 + mt * 16 + (lane >> 2);
            atomicAdd(&rowacc[lr], hs0);
            atomicAdd(&rowacc[lr + 8], hs1);
        }
        __syncthreads();
        if (tid < 128) {
            int gr = bm0 + tid;
            if (gr < NB * NN) {
                float contrib = rowacc[tid];
                if (blockIdx.x == 0) contrib += boutp[0];
                atomicAdd(&batchacc[gr / NN], contrib);
            }
        }
        __syncthreads();
        if (tid < 4) atomicAdd(&outp[tid], batchacc[tid] * (1.f / NN));
    }
}

// ---------------- LayerNorm (bf16 in/out) ----------------
__global__ void ln_kernel(const __nv_bfloat16* __restrict__ xin, __nv_bfloat16* __restrict__ yout,
                          const float* __restrict__ g, const float* __restrict__ bta) {
    int row = blockIdx.x;
    int t = threadIdx.x;
    __shared__ float red[4];
    uint2 u = *(const uint2*)(xin + (size_t)row * ND + t * 4);
    float v0 = bflo(u.x), v1 = bfhi(u.x), v2 = bflo(u.y), v3 = bfhi(u.y);

    float s = v0 + v1 + v2 + v3;
#pragma unroll
    for (int off = 16; off > 0; off >>= 1) s += __shfl_xor_sync(0xffffffff, s, off);
    if ((t & 31) == 0) red[t >> 5] = s;
    __syncthreads();
    float mu = (red[0] + red[1] + red[2] + red[3]) * (1.f / ND);
    __syncthreads();

    float d0 = v0 - mu, d1 = v1 - mu, d2 = v2 - mu, d3 = v3 - mu;
    float q = d0 * d0 + d1 * d1 + d2 * d2 + d3 * d3;
#pragma unroll
    for (int off = 16; off > 0; off >>= 1) q += __shfl_xor_sync(0xffffffff, q, off);
    if ((t & 31) == 0) red[t >> 5] = q;
    __syncthreads();
    float var = (red[0] + red[1] + red[2] + red[3]) * (1.f / ND);
    float rs  = rsqrtf(var + 1e-5f);

    float4 gg = ((const float4*)g)[t];
    float4 bb = ((const float4*)bta)[t];
    float o0 = d0 * rs * gg.x + bb.x;
    float o1 = d1 * rs * gg.y + bb.y;
    float o2 = d2 * rs * gg.z + bb.z;
    float o3 = d3 * rs * gg.w + bb.w;

    size_t ob = (size_t)row * ND + t * 4;
    *(__nv_bfloat162*)(yout + ob)     = __nv_bfloat162(__float2bfloat16(o0), __float2bfloat16(o1));
    *(__nv_bfloat162*)(yout + ob + 2) = __nv_bfloat162(__float2bfloat16(o2), __float2bfloat16(o3));
}

__global__ void zero_out_kernel(float* out) {
    if (threadIdx.x < NB) out[threadIdx.x] = 0.f;
}

// ---------------- launch ----------------
extern "C" void kernel_launch(void* const* d_in, const int* in_sizes, int n_in,
                              void* d_out, int out_size) {
    const int*   x_idx = (const int*)d_in[0];
    const int*   eidx  = (const int*)d_in[1];
    const float* ew    = (const float*)d_in[2];
    const float* emb   = (const float*)d_in[3];
    const float* W1    = (const float*)d_in[4];
    const float* b1    = (const float*)d_in[5];
    const float* g1    = (const float*)d_in[6];
    const float* be1   = (const float*)d_in[7];
    const float* W2    = (const float*)d_in[8];
    const float* b2    = (const float*)d_in[9];
    const float* ln_g  = (const float*)d_in[10];
    const float* ln_b  = (const float*)d_in[11];
    const float* Wm    = (const float*)d_in[12];
    const float* bm    = (const float*)d_in[13];
    const float* Wout  = (const float*)d_in[14];
    const float* bout  = (const float*)d_in[15];
    float* out = (float*)d_out;

    const int* src = eidx;
    const int* dst = eidx + NE;

    __nv_bfloat16 *pxb, *py, *ph, *w1hi, *w1lo, *w2hi, *w2lo, *wmhi, *wmlo;
    cudaGetSymbolAddress((void**)&pxb,  g_xb);
    cudaGetSymbolAddress((void**)&py,   g_y);
    cudaGetSymbolAddress((void**)&ph,   g_h);
    cudaGetSymbolAddress((void**)&w1hi, g_w1hi);
    cudaGetSymbolAddress((void**)&w1lo, g_w1lo);
    cudaGetSymbolAddress((void**)&w2hi, g_w2hi);
    cudaGetSymbolAddress((void**)&w2lo, g_w2lo);
    cudaGetSymbolAddress((void**)&wmhi, g_wmhi);
    cudaGetSymbolAddress((void**)&wmlo, g_wmlo);

    cudaFuncSetAttribute(bfgemm2_kernel<0>, cudaFuncAttributeMaxDynamicSharedMemorySize, GSMEM);
    cudaFuncSetAttribute(bfgemm2_kernel<1>, cudaFuncAttributeMaxDynamicSharedMemorySize, GSMEM);
    cudaFuncSetAttribute(bfgemm2_kernel<2>, cudaFuncAttributeMaxDynamicSharedMemorySize, GSMEM);
    cudaFuncSetAttribute(bfgemm2_kernel<3>, cudaFuncAttributeMaxDynamicSharedMemorySize, GSMEM);

    embed_count_kernel<<<(NB * NN * (ND / 4) + 255) / 256, 256>>>(x_idx, emb, dst);
    scan_deg_kernel<<<1, 1024>>>();
    scatter_edges_kernel<<<(NE + 255) / 256, 256>>>(dst, src, ew);
    msg_agg_kernel<<<NB * NN, 128>>>(pxb, py);   // layer 0
    transpose_split_all_kernel<<<dim3(32, 32, 2 * NL + NLM), dim3(32, 8)>>>(W1, W2, Wm);

    const dim3 g1grid(2 * ND / 64, MP / 128);   // 16 x 157
    const dim3 g2grid(ND / 64,     MP / 128);   //  8 x 157

    for (int l = 0; l < NL; l++) {
        if (l > 0) msg_agg_kernel<<<NB * NN, 128>>>(pxb, py);
        bfgemm2_kernel<0><<<g1grid, 256, GSMEM>>>(
            2 * ND, ND, py,
            w1hi + (size_t)l * 2 * ND * ND, w1lo + (size_t)l * 2 * ND * ND,
            ph,
            b1 + (size_t)l * 2 * ND, g1 + (size_t)l * 2 * ND, be1 + (size_t)l * 2 * ND,
            nullptr, nullptr, nullptr);
        bfgemm2_kernel<1><<<g2grid, 256, GSMEM>>>(
            ND, 2 * ND, ph,
            w2hi + (size_t)l * ND * 2 * ND, w2lo + (size_t)l * ND * 2 * ND,
            pxb,
            b2 + (size_t)l * ND, nullptr, nullptr,
            nullptr, nullptr, nullptr);
    }

    ln_kernel<<<NB * NN, 128>>>(pxb, py, ln_g, ln_b);

    bfgemm2_kernel<2><<<g2grid, 256, GSMEM>>>(
        ND, ND, py, wmhi, wmlo, ph, bm, nullptr, nullptr, nullptr, nullptr, nullptr);
    bfgemm2_kernel<2><<<g2grid, 256, GSMEM>>>(
        ND, ND, ph, wmhi + (size_t)ND * ND, wmlo + (size_t)ND * ND,
        py, bm + ND, nullptr, nullptr, nullptr, nullptr, nullptr);

    zero_out_kernel<<<1, 32>>>(out);
    bfgemm2_kernel<3><<<g2grid, 256, GSMEM>>>(
        ND, ND, py, wmhi + (size_t)2 * ND * ND, wmlo + (size_t)2 * ND * ND,
        nullptr, bm + 2 * ND, nullptr, nullptr, Wout, bout, out);
}